// round 6
// baseline (speedup 1.0000x reference)
#include <cuda_runtime.h>
#include <cstddef>

// Problem constants (fixed by setup_inputs)
#define BB 2
#define DD 48
#define HH 320
#define WW 640
#define RR 2
#define KK 5
#define K2 25
#define HW (HH * WW)

// Tiling: 16x32 output tile, 256 threads, 2 vertical pixels per thread,
// DC=16 disparities/chunk so 3 blocks fit per SM (24 warps).
#define TH 16
#define TW 32
#define DC 16
#define PH (TH + 2 * RR)   // 20
#define PW (TW + 2 * RR)   // 36
#define PD (DC + 2)        // 18 planes used
#define PDP 20             // plane stride (80B -> conflict-free LDS.128)
#define NT 256
#define SMEM_BYTES (PH * PW * PDP * 4)   // 57600

// Intermediate buffer for pass-1 result (allocation-free scratch)
__device__ float g_y[(size_t)BB * DD * HH * WW];

__device__ __forceinline__ unsigned long long pk2(float lo, float hi) {
    unsigned long long r;
    asm("mov.b64 %0, {%1, %2};" : "=l"(r) : "f"(lo), "f"(hi));
    return r;
}
__device__ __forceinline__ void ffma2(unsigned long long &acc,
                                      unsigned long long a,
                                      unsigned long long b) {
    asm("fma.rn.f32x2 %0, %1, %2, %0;" : "+l"(acc) : "l"(a), "l"(b));
}
__device__ __forceinline__ void upk2(unsigned long long v, float &lo, float &hi) {
    asm("mov.b64 {%0, %1}, %2;" : "=f"(lo), "=f"(hi) : "l"(v));
}

union Q4 { float4 f; unsigned long long u[2]; };
union Q2 { float2 f; unsigned long long u; };

__global__ void __launch_bounds__(NT, 3)
lga_kernel(const float* __restrict__ xin,
           const float* __restrict__ wts,
           float* __restrict__ xout)
{
    extern __shared__ float xs[];   // [PH][PW][PDP]

    const int t  = threadIdx.x;
    const int tx = t & 31;       // W within tile
    const int ty = t >> 5;       // 0..7 -> output rows 2ty, 2ty+1

    const int w0p = blockIdx.x * TW;
    const int h0  = blockIdx.y * TH;
    const int b   = blockIdx.z;

    const int gh0 = h0 + 2 * ty;
    const int gw  = w0p + tx;

    // weight base: wts[b, c, gh, gw], channel stride = HW
    const float* wb0 = wts + ((size_t)b * (3 * K2)) * HW + (size_t)gh0 * WW + gw;
    const float* wb1 = wb0 + WW;   // row gh0+1

    #pragma unroll 1
    for (int chunk = 0; chunk < DD / DC; ++chunk) {
        const int d0 = chunk * DC;

        __syncthreads();   // protect xs from previous chunk's readers

        // ---- fill shared slab, plane-contiguous: xs[(row*PW+col)*PDP + p] ----
        for (int pos = t; pos < PH * PW; pos += NT) {
            const int row = pos / PW;
            const int col = pos - row * PW;
            const int hh = h0 + row - RR;
            const int ww = w0p + col - RR;
            const bool sok = ((unsigned)hh < HH) & ((unsigned)ww < WW);
            const float* src = xin + ((size_t)b * DD * HH + hh) * (size_t)WW + ww;

            float buf[PDP];
            #pragma unroll
            for (int p = 0; p < PD; ++p) {
                const int gd = d0 - 1 + p;
                float v = 0.0f;
                if (sok && (unsigned)gd < DD) v = __ldg(src + (size_t)gd * HW);
                buf[p] = v;
            }
            buf[PD] = 0.0f; buf[PD + 1] = 0.0f;

            float4* dst = (float4*)&xs[pos * PDP];
            #pragma unroll
            for (int q = 0; q < PDP / 4; ++q)
                dst[q] = make_float4(buf[4*q], buf[4*q+1], buf[4*q+2], buf[4*q+3]);
        }
        __syncthreads();

        // ---- two vertically adjacent pixels per thread ----
        unsigned long long acc0[DC / 2], acc1[DC / 2];
        #pragma unroll
        for (int k = 0; k < DC / 2; ++k) { acc0[k] = 0ull; acc1[k] = 0ull; }

        // slab row for pixel0 tap (i,j): 2ty+i ; pixel1 tap (i,j): 2ty+1+i.
        // Union over both pixels: slab rows 2ty + i, i = 0..5.
        #pragma unroll
        for (int i = 0; i < KK + 1; ++i) {
            // per-(row,group) pointers: inner offsets j*HW fold into LDG immediates
            const float* p0a = wb0 + (size_t)(0 * K2 + i * KK) * HW;
            const float* p1a = wb0 + (size_t)(1 * K2 + i * KK) * HW;
            const float* p2a = wb0 + (size_t)(2 * K2 + i * KK) * HW;
            const float* p0b = wb1 + (size_t)(0 * K2 + (i - 1) * KK) * HW;
            const float* p1b = wb1 + (size_t)(1 * K2 + (i - 1) * KK) * HW;
            const float* p2b = wb1 + (size_t)(2 * K2 + (i - 1) * KK) * HW;

            #pragma unroll
            for (int j = 0; j < KK; ++j) {
                // disparity column at slab (2ty+i, tx+j); 80B lane stride
                const float* cb = &xs[((2 * ty + i) * PW + (tx + j)) * PDP];
                Q4 a0, a1, a2, a3; Q2 a4;
                a0.f = *(const float4*)(cb + 0);
                a1.f = *(const float4*)(cb + 4);
                a2.f = *(const float4*)(cb + 8);
                a3.f = *(const float4*)(cb + 12);
                a4.f = *(const float2*)(cb + 16);

                const unsigned long long E[9] = {
                    a0.u[0], a0.u[1], a1.u[0], a1.u[1],
                    a2.u[0], a2.u[1], a3.u[0], a3.u[1], a4.u
                };
                const float c[PD] = {
                    a0.f.x, a0.f.y, a0.f.z, a0.f.w,
                    a1.f.x, a1.f.y, a1.f.z, a1.f.w,
                    a2.f.x, a2.f.y, a2.f.z, a2.f.w,
                    a3.f.x, a3.f.y, a3.f.z, a3.f.w,
                    a4.f.x, a4.f.y
                };

                unsigned long long W0a = 0, W1a = 0, W2a = 0;
                unsigned long long W0b = 0, W1b = 0, W2b = 0;
                if (i < KK) {            // pixel0 tap (i, j)
                    const float wt0 = __ldg(p0a + (size_t)j * HW);
                    const float wt1 = __ldg(p1a + (size_t)j * HW);
                    const float wt2 = __ldg(p2a + (size_t)j * HW);
                    W0a = pk2(wt0, wt0); W1a = pk2(wt1, wt1); W2a = pk2(wt2, wt2);
                }
                if (i >= 1) {            // pixel1 tap (i-1, j)
                    const float wt0 = __ldg(p0b + (size_t)j * HW);
                    const float wt1 = __ldg(p1b + (size_t)j * HW);
                    const float wt2 = __ldg(p2b + (size_t)j * HW);
                    W0b = pk2(wt0, wt0); W1b = pk2(wt1, wt1); W2b = pk2(wt2, wt2);
                }

                #pragma unroll
                for (int k = 0; k < DC / 2; ++k) {
                    // acc pair covers d = d0+2k, d0+2k+1 ; c[p] = x[d0-1+p]
                    const unsigned long long O = pk2(c[2*k + 1], c[2*k + 2]);
                    if (i < KK) {
                        ffma2(acc0[k], W1a, E[k]);       // x[d-1]
                        ffma2(acc0[k], W0a, O);          // x[d]
                        ffma2(acc0[k], W2a, E[k + 1]);   // x[d+1]
                    }
                    if (i >= 1) {
                        ffma2(acc1[k], W1b, E[k]);
                        ffma2(acc1[k], W0b, O);
                        ffma2(acc1[k], W2b, E[k + 1]);
                    }
                }
            }
        }

        // ---- write out (coalesced along tx) ----
        float* outp0 = xout + (((size_t)b * DD + d0) * HH + gh0) * (size_t)WW + gw;
        float* outp1 = outp0 + WW;
        #pragma unroll
        for (int k = 0; k < DC / 2; ++k) {
            float lo, hi;
            upk2(acc0[k], lo, hi);
            outp0[(size_t)(2 * k) * HW]     = lo;
            outp0[(size_t)(2 * k + 1) * HW] = hi;
            upk2(acc1[k], lo, hi);
            outp1[(size_t)(2 * k) * HW]     = lo;
            outp1[(size_t)(2 * k + 1) * HW] = hi;
        }
    }
}

extern "C" void kernel_launch(void* const* d_in, const int* in_sizes, int n_in,
                              void* d_out, int out_size)
{
    const float* x = (const float*)d_in[0];   // [B, D, H, W]
    const float* w = (const float*)d_in[1];   // [B, 75, H, W]
    float* out = (float*)d_out;

    float* ybuf = nullptr;
    cudaGetSymbolAddress((void**)&ybuf, g_y);

    cudaFuncSetAttribute(lga_kernel,
                         cudaFuncAttributeMaxDynamicSharedMemorySize, SMEM_BYTES);

    dim3 grid(WW / TW, HH / TH, BB);   // 20 x 20 x 2
    lga_kernel<<<grid, NT, SMEM_BYTES>>>(x, w, ybuf);   // pass 1
    lga_kernel<<<grid, NT, SMEM_BYTES>>>(ybuf, w, out); // pass 2
}

// round 7
// speedup vs baseline: 1.3885x; 1.3885x over previous
#include <cuda_runtime.h>
#include <cstddef>

// Problem constants (fixed by setup_inputs)
#define BB 2
#define DD 48
#define HH 320
#define WW 640
#define RR 2
#define KK 5
#define K2 25
#define HW (HH * WW)

// Tiling: 20x32 output tile, 320 threads, 2 vertical pixels per thread.
// 2 blocks/SM -> 20 warps, reg cap 102 (natural ~112, mild shave).
#define TH 20
#define TW 32
#define DC 16
#define PH (TH + 2 * RR)   // 24
#define PW (TW + 2 * RR)   // 36
#define PD (DC + 2)        // 18 planes used
#define PDP 20             // plane stride (80B -> conflict-free LDS.128)
#define NT 320
#define SMEM_BYTES (PH * PW * PDP * 4)   // 69120

// Intermediate buffer for pass-1 result (allocation-free scratch)
__device__ float g_y[(size_t)BB * DD * HH * WW];

__device__ __forceinline__ unsigned long long pk2(float lo, float hi) {
    unsigned long long r;
    asm("mov.b64 %0, {%1, %2};" : "=l"(r) : "f"(lo), "f"(hi));
    return r;
}
__device__ __forceinline__ void ffma2(unsigned long long &acc,
                                      unsigned long long a,
                                      unsigned long long b) {
    asm("fma.rn.f32x2 %0, %1, %2, %0;" : "+l"(acc) : "l"(a), "l"(b));
}
__device__ __forceinline__ void upk2(unsigned long long v, float &lo, float &hi) {
    asm("mov.b64 {%0, %1}, %2;" : "=f"(lo), "=f"(hi) : "l"(v));
}

union Q4 { float4 f; unsigned long long u[2]; };
union Q2 { float2 f; unsigned long long u; };

__global__ void __launch_bounds__(NT, 2)
lga_kernel(const float* __restrict__ xin,
           const float* __restrict__ wts,
           float* __restrict__ xout)
{
    extern __shared__ float xs[];   // [PH][PW][PDP]

    const int t  = threadIdx.x;
    const int tx = t & 31;       // W within tile
    const int ty = t >> 5;       // 0..9 -> output rows 2ty, 2ty+1

    const int w0p = blockIdx.x * TW;
    const int h0  = blockIdx.y * TH;
    const int b   = blockIdx.z;

    const int gh0 = h0 + 2 * ty;
    const int gw  = w0p + tx;

    // weight base: wts[b, c, gh, gw], channel stride = HW
    const float* wb0 = wts + ((size_t)b * (3 * K2)) * HW + (size_t)gh0 * WW + gw;
    const float* wb1 = wb0 + WW;   // row gh0+1

    #pragma unroll 1
    for (int chunk = 0; chunk < DD / DC; ++chunk) {
        const int d0 = chunk * DC;

        __syncthreads();   // protect xs from previous chunk's readers

        // ---- fill shared slab, plane-contiguous: xs[(row*PW+col)*PDP + p] ----
        for (int pos = t; pos < PH * PW; pos += NT) {
            const int row = pos / PW;
            const int col = pos - row * PW;
            const int hh = h0 + row - RR;
            const int ww = w0p + col - RR;
            const bool sok = ((unsigned)hh < HH) & ((unsigned)ww < WW);
            const float* src = xin + ((size_t)b * DD * HH + hh) * (size_t)WW + ww;

            float buf[PDP];
            #pragma unroll
            for (int p = 0; p < PD; ++p) {
                const int gd = d0 - 1 + p;
                float v = 0.0f;
                if (sok && (unsigned)gd < DD) v = __ldg(src + (size_t)gd * HW);
                buf[p] = v;
            }
            buf[PD] = 0.0f; buf[PD + 1] = 0.0f;

            float4* dst = (float4*)&xs[pos * PDP];
            #pragma unroll
            for (int q = 0; q < PDP / 4; ++q)
                dst[q] = make_float4(buf[4*q], buf[4*q+1], buf[4*q+2], buf[4*q+3]);
        }
        __syncthreads();

        // ---- two vertically adjacent pixels per thread ----
        unsigned long long acc0[DC / 2], acc1[DC / 2];
        #pragma unroll
        for (int k = 0; k < DC / 2; ++k) { acc0[k] = 0ull; acc1[k] = 0ull; }

        // slab row for pixel0 tap (i,j): 2ty+i ; pixel1 tap (i,j): 2ty+1+i.
        // Union over both pixels: slab rows 2ty + i, i = 0..5.
        #pragma unroll
        for (int i = 0; i < KK + 1; ++i) {
            // per-(row,group) pointers: inner offsets j*HW fold into LDG immediates
            const float* p0a = wb0 + (size_t)(0 * K2 + i * KK) * HW;
            const float* p1a = wb0 + (size_t)(1 * K2 + i * KK) * HW;
            const float* p2a = wb0 + (size_t)(2 * K2 + i * KK) * HW;
            const float* p0b = wb1 + (size_t)(0 * K2 + (i - 1) * KK) * HW;
            const float* p1b = wb1 + (size_t)(1 * K2 + (i - 1) * KK) * HW;
            const float* p2b = wb1 + (size_t)(2 * K2 + (i - 1) * KK) * HW;

            #pragma unroll
            for (int j = 0; j < KK; ++j) {
                // disparity column at slab (2ty+i, tx+j); 80B lane stride
                const float* cb = &xs[((2 * ty + i) * PW + (tx + j)) * PDP];
                Q4 a0, a1, a2, a3; Q2 a4;
                a0.f = *(const float4*)(cb + 0);
                a1.f = *(const float4*)(cb + 4);
                a2.f = *(const float4*)(cb + 8);
                a3.f = *(const float4*)(cb + 12);
                a4.f = *(const float2*)(cb + 16);

                const unsigned long long E[9] = {
                    a0.u[0], a0.u[1], a1.u[0], a1.u[1],
                    a2.u[0], a2.u[1], a3.u[0], a3.u[1], a4.u
                };
                const float c[PD] = {
                    a0.f.x, a0.f.y, a0.f.z, a0.f.w,
                    a1.f.x, a1.f.y, a1.f.z, a1.f.w,
                    a2.f.x, a2.f.y, a2.f.z, a2.f.w,
                    a3.f.x, a3.f.y, a3.f.z, a3.f.w,
                    a4.f.x, a4.f.y
                };

                unsigned long long W0a = 0, W1a = 0, W2a = 0;
                unsigned long long W0b = 0, W1b = 0, W2b = 0;
                if (i < KK) {            // pixel0 tap (i, j)
                    const float wt0 = __ldg(p0a + (size_t)j * HW);
                    const float wt1 = __ldg(p1a + (size_t)j * HW);
                    const float wt2 = __ldg(p2a + (size_t)j * HW);
                    W0a = pk2(wt0, wt0); W1a = pk2(wt1, wt1); W2a = pk2(wt2, wt2);
                }
                if (i >= 1) {            // pixel1 tap (i-1, j)
                    const float wt0 = __ldg(p0b + (size_t)j * HW);
                    const float wt1 = __ldg(p1b + (size_t)j * HW);
                    const float wt2 = __ldg(p2b + (size_t)j * HW);
                    W0b = pk2(wt0, wt0); W1b = pk2(wt1, wt1); W2b = pk2(wt2, wt2);
                }

                #pragma unroll
                for (int k = 0; k < DC / 2; ++k) {
                    // acc pair covers d = d0+2k, d0+2k+1 ; c[p] = x[d0-1+p]
                    const unsigned long long O = pk2(c[2*k + 1], c[2*k + 2]);
                    if (i < KK) {
                        ffma2(acc0[k], W1a, E[k]);       // x[d-1]
                        ffma2(acc0[k], W0a, O);          // x[d]
                        ffma2(acc0[k], W2a, E[k + 1]);   // x[d+1]
                    }
                    if (i >= 1) {
                        ffma2(acc1[k], W1b, E[k]);
                        ffma2(acc1[k], W0b, O);
                        ffma2(acc1[k], W2b, E[k + 1]);
                    }
                }
            }
        }

        // ---- write out (coalesced along tx) ----
        float* outp0 = xout + (((size_t)b * DD + d0) * HH + gh0) * (size_t)WW + gw;
        float* outp1 = outp0 + WW;
        #pragma unroll
        for (int k = 0; k < DC / 2; ++k) {
            float lo, hi;
            upk2(acc0[k], lo, hi);
            outp0[(size_t)(2 * k) * HW]     = lo;
            outp0[(size_t)(2 * k + 1) * HW] = hi;
            upk2(acc1[k], lo, hi);
            outp1[(size_t)(2 * k) * HW]     = lo;
            outp1[(size_t)(2 * k + 1) * HW] = hi;
        }
    }
}

extern "C" void kernel_launch(void* const* d_in, const int* in_sizes, int n_in,
                              void* d_out, int out_size)
{
    const float* x = (const float*)d_in[0];   // [B, D, H, W]
    const float* w = (const float*)d_in[1];   // [B, 75, H, W]
    float* out = (float*)d_out;

    float* ybuf = nullptr;
    cudaGetSymbolAddress((void**)&ybuf, g_y);

    cudaFuncSetAttribute(lga_kernel,
                         cudaFuncAttributeMaxDynamicSharedMemorySize, SMEM_BYTES);

    dim3 grid(WW / TW, HH / TH, BB);   // 20 x 16 x 2
    lga_kernel<<<grid, NT, SMEM_BYTES>>>(x, w, ybuf);   // pass 1
    lga_kernel<<<grid, NT, SMEM_BYTES>>>(ybuf, w, out); // pass 2
}

// round 8
// speedup vs baseline: 1.5746x; 1.1340x over previous
#include <cuda_runtime.h>
#include <cstddef>

// Problem constants (fixed by setup_inputs)
#define BB 2
#define DD 48
#define HH 320
#define WW 640
#define RR 2
#define KK 5
#define K2 25
#define HW (HH * WW)

// Tiling: 16x32 output tile, 256 threads, 2 vertical pixels per thread
#define TH 16
#define TW 32
#define DC 24              // disparities per chunk (2 chunks)
#define PH (TH + 2 * RR)   // 20
#define PW (TW + 2 * RR)   // 36
#define PD (DC + 2)        // 26 planes used
#define PDP 28             // plane stride (112B -> conflict-free LDS.128)
#define NT 256
#define SMEM_BYTES (PH * PW * PDP * 4)   // 80640

// Intermediate buffer for pass-1 result (allocation-free scratch)
__device__ float g_y[(size_t)BB * DD * HH * WW];

__device__ __forceinline__ unsigned long long pk2(float lo, float hi) {
    unsigned long long r;
    asm("mov.b64 %0, {%1, %2};" : "=l"(r) : "f"(lo), "f"(hi));
    return r;
}
__device__ __forceinline__ void ffma2(unsigned long long &acc,
                                      unsigned long long a,
                                      unsigned long long b) {
    asm("fma.rn.f32x2 %0, %1, %2, %0;" : "+l"(acc) : "l"(a), "l"(b));
}
__device__ __forceinline__ void upk2(unsigned long long v, float &lo, float &hi) {
    asm("mov.b64 {%0, %1}, %2;" : "=f"(lo), "=f"(hi) : "l"(v));
}

union Q4 { float4 f; unsigned long long u[2]; float s[4]; };
union Q2 { float2 f; unsigned long long u; float s[2]; };

__global__ void __launch_bounds__(NT, 2)
lga_kernel(const float* __restrict__ xin,
           const float* __restrict__ wts,
           float* __restrict__ xout)
{
    extern __shared__ float xs[];   // [PH][PW][PDP]

    const int t  = threadIdx.x;
    const int tx = t & 31;       // W within tile
    const int ty = t >> 5;       // 0..7 -> output rows 2ty, 2ty+1

    const int w0p = blockIdx.x * TW;
    const int h0  = blockIdx.y * TH;
    const int b   = blockIdx.z;

    const int gh0 = h0 + 2 * ty;
    const int gw  = w0p + tx;

    // weight base: wts[b, c, gh, gw], channel stride = HW
    const float* wb0 = wts + ((size_t)b * (3 * K2)) * HW + (size_t)gh0 * WW + gw;
    const float* wb1 = wb0 + WW;   // row gh0+1

    // thread's column base in the slab; per-tap offset is a compile-time const
    float* const xsb = &xs[(2 * ty * PW + tx) * PDP];

    #pragma unroll 1
    for (int chunk = 0; chunk < DD / DC; ++chunk) {
        const int d0 = chunk * DC;

        __syncthreads();   // protect xs from previous chunk's readers

        // ---- fill shared slab, plane-contiguous: xs[(row*PW+col)*PDP + p] ----
        for (int pos = t; pos < PH * PW; pos += NT) {
            const int row = pos / PW;
            const int col = pos - row * PW;
            const int hh = h0 + row - RR;
            const int ww = w0p + col - RR;
            const bool sok = ((unsigned)hh < HH) & ((unsigned)ww < WW);
            const float* src = xin + ((size_t)b * DD * HH + hh) * (size_t)WW + ww;

            float buf[PDP];
            #pragma unroll
            for (int p = 0; p < PD; ++p) {
                const int gd = d0 - 1 + p;
                float v = 0.0f;
                if (sok && (unsigned)gd < DD) v = __ldg(src + (size_t)gd * HW);
                buf[p] = v;
            }
            buf[PD] = 0.0f; buf[PD + 1] = 0.0f;

            float4* dst = (float4*)&xs[pos * PDP];
            #pragma unroll
            for (int q = 0; q < PDP / 4; ++q)
                dst[q] = make_float4(buf[4*q], buf[4*q+1], buf[4*q+2], buf[4*q+3]);
        }
        __syncthreads();

        // ---- two vertically adjacent pixels per thread ----
        unsigned long long acc0[DC / 2], acc1[DC / 2];
        #pragma unroll
        for (int k = 0; k < DC / 2; ++k) { acc0[k] = 0ull; acc1[k] = 0ull; }

        // pixel0 tap (i,j) -> slab row 2ty+i ; pixel1 tap (i,j) -> row 2ty+1+i.
        // Union: slab rows 2ty+i, i=0..5. Weight loads are software-pipelined
        // one j-tap ahead inside each i-row.
        #pragma unroll
        for (int i = 0; i < KK + 1; ++i) {
            // per-(row,group) pointers: j*HW offsets fold into LDG immediates
            const float* p0a = wb0 + (size_t)(0 * K2 + i * KK) * HW;
            const float* p1a = wb0 + (size_t)(1 * K2 + i * KK) * HW;
            const float* p2a = wb0 + (size_t)(2 * K2 + i * KK) * HW;
            const float* p0b = wb1 + (size_t)(0 * K2 + (i - 1) * KK) * HW;
            const float* p1b = wb1 + (size_t)(1 * K2 + (i - 1) * KK) * HW;
            const float* p2b = wb1 + (size_t)(2 * K2 + (i - 1) * KK) * HW;

            // prime the weight pipeline with tap j=0
            float c0a = 0, c1a = 0, c2a = 0, c0b = 0, c1b = 0, c2b = 0;
            if (i < KK) {
                c0a = __ldcs(p0a); c1a = __ldcs(p1a); c2a = __ldcs(p2a);
            }
            if (i >= 1) {
                c0b = __ldcs(p0b); c1b = __ldcs(p1b); c2b = __ldcs(p2b);
            }

            #pragma unroll
            for (int j = 0; j < KK; ++j) {
                // prefetch next tap's weights while computing this tap
                float n0a = 0, n1a = 0, n2a = 0, n0b = 0, n1b = 0, n2b = 0;
                if (j + 1 < KK) {
                    if (i < KK) {
                        n0a = __ldcs(p0a + (size_t)(j + 1) * HW);
                        n1a = __ldcs(p1a + (size_t)(j + 1) * HW);
                        n2a = __ldcs(p2a + (size_t)(j + 1) * HW);
                    }
                    if (i >= 1) {
                        n0b = __ldcs(p0b + (size_t)(j + 1) * HW);
                        n1b = __ldcs(p1b + (size_t)(j + 1) * HW);
                        n2b = __ldcs(p2b + (size_t)(j + 1) * HW);
                    }
                }

                unsigned long long W0a = 0, W1a = 0, W2a = 0;
                unsigned long long W0b = 0, W1b = 0, W2b = 0;
                if (i < KK) { W0a = pk2(c0a, c0a); W1a = pk2(c1a, c1a); W2a = pk2(c2a, c2a); }
                if (i >= 1) { W0b = pk2(c0b, c0b); W1b = pk2(c1b, c1b); W2b = pk2(c2b, c2b); }

                // column at compile-time slab offset; sliding 2-quad window
                const float* cb = xsb + (i * PW + j) * PDP;

                Q4 qa, qb; Q2 qt;
                qa.f = *(const float4*)(cb + 0);

                #pragma unroll
                for (int tq = 0; tq < DC / 4; ++tq) {
                    // load next quad (or tail pair) of the column
                    if (tq < DC / 4 - 1) {
                        qb.f = *(const float4*)(cb + 4 * (tq + 1));
                    } else {
                        qt.f = *(const float2*)(cb + DC);   // c[DC], c[DC+1]
                        qb.u[0] = qt.u;
                    }
                    // k = 2*tq : E=qa.u[0], O=(qa.y,qa.z), E'=qa.u[1]
                    {
                        const int k = 2 * tq;
                        const unsigned long long O = pk2(qa.s[1], qa.s[2]);
                        if (i < KK) {
                            ffma2(acc0[k], W1a, qa.u[0]);
                            ffma2(acc0[k], W0a, O);
                            ffma2(acc0[k], W2a, qa.u[1]);
                        }
                        if (i >= 1) {
                            ffma2(acc1[k], W1b, qa.u[0]);
                            ffma2(acc1[k], W0b, O);
                            ffma2(acc1[k], W2b, qa.u[1]);
                        }
                    }
                    // k = 2*tq+1 : E=qa.u[1], O=(qa.w,qb.x), E'=qb.u[0]
                    {
                        const int k = 2 * tq + 1;
                        const unsigned long long O = pk2(qa.s[3], qb.s[0]);
                        if (i < KK) {
                            ffma2(acc0[k], W1a, qa.u[1]);
                            ffma2(acc0[k], W0a, O);
                            ffma2(acc0[k], W2a, qb.u[0]);
                        }
                        if (i >= 1) {
                            ffma2(acc1[k], W1b, qa.u[1]);
                            ffma2(acc1[k], W0b, O);
                            ffma2(acc1[k], W2b, qb.u[0]);
                        }
                    }
                    if (tq < DC / 4 - 1) {
                        qa.f = qb.f;
                    }
                }

                // rotate the weight pipeline
                c0a = n0a; c1a = n1a; c2a = n2a;
                c0b = n0b; c1b = n1b; c2b = n2b;
            }
        }

        // ---- write out (coalesced along tx) ----
        float* outp0 = xout + (((size_t)b * DD + d0) * HH + gh0) * (size_t)WW + gw;
        float* outp1 = outp0 + WW;
        #pragma unroll
        for (int k = 0; k < DC / 2; ++k) {
            float lo, hi;
            upk2(acc0[k], lo, hi);
            outp0[(size_t)(2 * k) * HW]     = lo;
            outp0[(size_t)(2 * k + 1) * HW] = hi;
            upk2(acc1[k], lo, hi);
            outp1[(size_t)(2 * k) * HW]     = lo;
            outp1[(size_t)(2 * k + 1) * HW] = hi;
        }
    }
}

extern "C" void kernel_launch(void* const* d_in, const int* in_sizes, int n_in,
                              void* d_out, int out_size)
{
    const float* x = (const float*)d_in[0];   // [B, D, H, W]
    const float* w = (const float*)d_in[1];   // [B, 75, H, W]
    float* out = (float*)d_out;

    float* ybuf = nullptr;
    cudaGetSymbolAddress((void**)&ybuf, g_y);

    cudaFuncSetAttribute(lga_kernel,
                         cudaFuncAttributeMaxDynamicSharedMemorySize, SMEM_BYTES);

    dim3 grid(WW / TW, HH / TH, BB);   // 20 x 20 x 2
    lga_kernel<<<grid, NT, SMEM_BYTES>>>(x, w, ybuf);   // pass 1
    lga_kernel<<<grid, NT, SMEM_BYTES>>>(ybuf, w, out); // pass 2
}